// round 13
// baseline (speedup 1.0000x reference)
#include <cuda_runtime.h>
#include <cuda_bf16.h>

// Problem constants (fixed shapes for this problem instance)
#define BB 1
#define NN 2048
#define CC 16
#define MM 2
#define HH 128
#define WW 128
#define HW (HH*WW)
#define NEARP 0.1f
#define FARP  100.0f

#define PVEC 6          // 6 float4 per gaussian: [u,v,ia,ib | ic,op,z,pad | sem0..15]
#define NT 64           // 8x8 tiles of 16x16 px per view
#define SSEG 4          // equal-length slices of each tile's list
#define NF 19           // partial record: depth, 16 sem, alpha, T
#define CUT2 20.0f      // d2 cutoff: skipped alpha < op*4.5e-5, ~20x under 1e-3 tol

__device__ float4 g_par [MM * NN * PVEC];   // per-(view,gaussian) packed params
__device__ float4 g_bbox[MM * NN];          // bbox (umin,umax,vmin,vmax), unsorted
__device__ int    g_perm[MM * NN];          // perm[rank] = gaussian index
__device__ int    g_list[MM * NT * NN];     // per-tile depth-ordered lists
__device__ int    g_cnt [MM * NT];          // per-tile list lengths
__device__ float  g_part[MM * NT * SSEG * NF * 256];  // segment partials

// ---------------------------------------------------------------------------
// Kernel 1: per-(view, gaussian) preprocessing (independent of sort)
// ---------------------------------------------------------------------------
__global__ void prep_kernel(const float* __restrict__ means,
                            const float* __restrict__ scales,
                            const float* __restrict__ rots,
                            const float* __restrict__ opac,
                            const float* __restrict__ sem,
                            const float* __restrict__ intr,
                            const float* __restrict__ c2e)
{
    int idx = blockIdx.x * blockDim.x + threadIdx.x;
    if (idx >= MM * NN) return;
    int m = idx / NN;
    int n = idx % NN;

    // cam2ego (rigid) -> ego2cam: E_R = R^T, E_t = -R^T t
    const float* A = c2e + m * 16;
    float a03=A[3], a13=A[7], a23=A[11];
    float w00=A[0], w01=A[4], w02=A[8];
    float w10=A[1], w11=A[5], w12=A[9];
    float w20=A[2], w21=A[6], w22=A[10];
    float e0 = -(w00*a03 + w01*a13 + w02*a23);
    float e1 = -(w10*a03 + w11*a13 + w12*a23);
    float e2 = -(w20*a03 + w21*a13 + w22*a23);

    float mx = means[n*3+0], my = means[n*3+1], mz = means[n*3+2];
    float xc = w00*mx + w01*my + w02*mz + e0;
    float yc = w10*mx + w11*my + w12*mz + e1;
    float zc = w20*mx + w21*my + w22*mz + e2;

    const float* K = intr + m * 16;
    float fx = K[0], cx = K[2], fy = K[5], cy = K[6];

    float zs = fmaxf(zc, 1e-4f);
    float u = xc / zs * fx + cx;
    float v = yc / zs * fy + cy;

    // quaternion (w,x,y,z) -> rotation matrix
    float qw = rots[n*4+0], qx = rots[n*4+1], qy = rots[n*4+2], qz = rots[n*4+3];
    float qn = rsqrtf(qw*qw + qx*qx + qy*qy + qz*qz);
    qw *= qn; qx *= qn; qy *= qn; qz *= qn;
    float r00 = 1.f - 2.f*(qy*qy + qz*qz);
    float r01 = 2.f*(qx*qy - qz*qw);
    float r02 = 2.f*(qx*qz + qy*qw);
    float r10 = 2.f*(qx*qy + qz*qw);
    float r11 = 1.f - 2.f*(qx*qx + qz*qz);
    float r12 = 2.f*(qy*qz - qx*qw);
    float r20 = 2.f*(qx*qz - qy*qw);
    float r21 = 2.f*(qy*qz + qx*qw);
    float r22 = 1.f - 2.f*(qx*qx + qy*qy);

    float s0 = scales[n*3+0], s1 = scales[n*3+1], s2 = scales[n*3+2];
    float m00=r00*s0, m01=r01*s1, m02=r02*s2;
    float m10=r10*s0, m11=r11*s1, m12=r12*s2;
    float m20=r20*s0, m21=r21*s1, m22=r22*s2;
    // Sigma = RS RS^T
    float S00 = m00*m00 + m01*m01 + m02*m02;
    float S01 = m00*m10 + m01*m11 + m02*m12;
    float S02 = m00*m20 + m01*m21 + m02*m22;
    float S11 = m10*m10 + m11*m11 + m12*m12;
    float S12 = m10*m20 + m11*m21 + m12*m22;
    float S22 = m20*m20 + m21*m21 + m22*m22;

    // Sigma_cam = Wc * Sigma * Wc^T
    float t00 = w00*S00 + w01*S01 + w02*S02;
    float t01 = w00*S01 + w01*S11 + w02*S12;
    float t02 = w00*S02 + w01*S12 + w02*S22;
    float t10 = w10*S00 + w11*S01 + w12*S02;
    float t11 = w10*S01 + w11*S11 + w12*S12;
    float t12 = w10*S02 + w11*S12 + w12*S22;
    float t20 = w20*S00 + w21*S01 + w22*S02;
    float t21 = w20*S01 + w21*S11 + w22*S12;
    float t22 = w20*S02 + w21*S12 + w22*S22;
    float c00 = t00*w00 + t01*w01 + t02*w02;
    float c01 = t00*w10 + t01*w11 + t02*w12;
    float c02 = t00*w20 + t01*w21 + t02*w22;
    float c11 = t10*w10 + t11*w11 + t12*w12;
    float c12 = t10*w20 + t11*w21 + t12*w22;
    float c22 = t20*w20 + t21*w21 + t22*w22;

    // J projection
    float iz = 1.f / zs;
    float jx = fx * iz;
    float jy = fy * iz;
    float jz0 = -fx * xc * iz * iz;
    float jz1 = -fy * yc * iz * iz;

    float cov00 = jx*jx*c00 + 2.f*jx*jz0*c02 + jz0*jz0*c22;
    float cov01 = jx*jy*c01 + jx*jz1*c02 + jz0*jy*c12 + jz0*jz1*c22;
    float cov11 = jy*jy*c11 + 2.f*jy*jz1*c12 + jz1*jz1*c22;

    float aa = fmaxf(cov00, 0.3f);
    float cc = fmaxf(cov11, 0.3f);
    float bb = cov01;
    float det = aa*cc - bb*bb;
    bool valid = (zc > 0.01f) && (det > 1e-8f);
    float dets = (det > 1e-8f) ? det : 1.f;
    float ia =  cc / dets;
    float ib = -bb / dets;
    float ic =  aa / dets;

    bool visible = valid && (zc > NEARP) &&
                   (u >= 0.f) && (u < (float)WW) &&
                   (v >= 0.f) && (v < (float)HH);

    float op = visible ? opac[n] : 0.f;

    // bbox of the d2<CUT2 ellipse (axis-aligned extents)
    float ex = sqrtf(CUT2 * aa);
    float ey = sqrtf(CUT2 * cc);
    float4 bbx;
    if (visible) bbx = make_float4(u - ex, u + ex, v - ey, v + ey);
    else         bbx = make_float4(1e9f, -1e9f, 1e9f, -1e9f);
    g_bbox[m * NN + n] = bbx;

    float* P = (float*)(g_par + (m * NN + n) * PVEC);
    P[0] = u; P[1] = v; P[2] = ia; P[3] = ib;
    P[4] = ic; P[5] = op;
    P[6] = fminf(fmaxf(zc, NEARP), FARP);
    P[7] = 0.f;
    const float* sm = sem + n * CC;
    #pragma unroll
    for (int c = 0; c < CC; c++) P[8 + c] = sm[c];
}

// ---------------------------------------------------------------------------
// Kernel 2: warp-per-gaussian stable rank sort (z ascending, index tiebreak).
// Computes z directly from means/c2e (no dependency on prep!). Writes perm.
// grid (NN/8, MM), block 256 (8 warps)
// ---------------------------------------------------------------------------
__global__ void sort_kernel(const float* __restrict__ means,
                            const float* __restrict__ c2e)
{
    int m    = blockIdx.y;
    int t    = threadIdx.x;
    int lane = t & 31;
    int n    = blockIdx.x * 8 + (t >> 5);

    const float* A = c2e + m * 16;
    float w20 = A[2], w21 = A[6], w22 = A[10];
    float e2  = -(w20 * A[3] + w21 * A[7] + w22 * A[11]);

    __shared__ unsigned ks[NN];
    for (int i = t; i < NN; i += 256) {
        float zc = w20 * means[i*3+0] + w21 * means[i*3+1] + w22 * means[i*3+2] + e2;
        unsigned b = __float_as_uint(zc);
        ks[i] = b ^ (unsigned)(((int)b >> 31) | 0x80000000);  // monotonic key
    }
    __syncthreads();

    unsigned ki = ks[n];
    int r = 0;
    #pragma unroll 8
    for (int j = lane; j < NN; j += 32) {
        unsigned kj = ks[j];
        r += (kj < ki) || (kj == ki && j < n);
    }
    #pragma unroll
    for (int o = 16; o > 0; o >>= 1) r += __shfl_xor_sync(0xffffffffu, r, o);

    if (lane == 0) g_perm[m * NN + r] = n;
}

// ---------------------------------------------------------------------------
// Kernel 3: binning. One block (4 warps) per (view, tile). Each warp compacts
// its depth-quarter (gathering bbox via perm); block prefix; coalesced copy
// into one depth-ordered per-tile list. grid MM*NT = 128 blocks, 128 threads.
// ---------------------------------------------------------------------------
#define QN (NN / 4)     // 512 entries per warp-quarter

__global__ void bin_kernel()
{
    int m    = blockIdx.x / NT;
    int tile = blockIdx.x % NT;
    int wid  = threadIdx.x >> 5;
    int lane = threadIdx.x & 31;

    __shared__ int sh_idx[NN];      // 4 quarters x 512
    __shared__ int sh_cnt[4];

    float x0 = (float)((tile & 7) * 16);
    float y0 = (float)((tile >> 3) * 16);
    float x1 = x0 + 15.f;
    float y1 = y0 + 15.f;

    int base = wid * QN;
    int cnt = 0;
    #pragma unroll 4
    for (int it = 0; it < QN / 32; it++) {
        int j = base + it * 32 + lane;
        int idx = g_perm[m * NN + j];
        float4 bb = g_bbox[m * NN + idx];
        bool hit = (bb.x <= x1) && (bb.y >= x0) && (bb.z <= y1) && (bb.w >= y0);
        unsigned msk = __ballot_sync(0xffffffffu, hit);
        if (hit) sh_idx[base + cnt + __popc(msk & ((1u << lane) - 1u))] = idx;
        cnt += __popc(msk);
    }
    if (lane == 0) sh_cnt[wid] = cnt;
    __syncthreads();

    int c0 = sh_cnt[0], c1 = sh_cnt[1], c2 = sh_cnt[2], c3 = sh_cnt[3];
    int off1 = c0, off2 = c0 + c1, off3 = c0 + c1 + c2;
    int total = off3 + c3;

    int* lp = g_list + (m * NT + tile) * NN;
    for (int i = threadIdx.x; i < c0; i += 128) lp[i]        = sh_idx[0*QN + i];
    for (int i = threadIdx.x; i < c1; i += 128) lp[off1 + i] = sh_idx[1*QN + i];
    for (int i = threadIdx.x; i < c2; i += 128) lp[off2 + i] = sh_idx[2*QN + i];
    for (int i = threadIdx.x; i < c3; i += 128) lp[off3 + i] = sh_idx[3*QN + i];
    if (threadIdx.x == 0) g_cnt[m * NT + tile] = total;
}

// ---------------------------------------------------------------------------
// Kernel 4: segmented front-to-back compositing (16x16 px tile, 256 threads).
// Equal-length slices of each tile's depth-ordered list; segment-local T.
// grid (8, 8, MM*SSEG), block 256.
// ---------------------------------------------------------------------------
#define CHUNK 128

__global__ void __launch_bounds__(256, 4) render_kernel()
{
    int mz  = blockIdx.z;
    int m   = mz / SSEG;
    int seg = mz % SSEG;
    int t   = threadIdx.x;
    float fpx = (float)(blockIdx.x * 16 + (t & 15));
    float fpy = (float)(blockIdx.y * 16 + (t >> 4));

    int tile = blockIdx.y * 8 + blockIdx.x;
    const int* lp = g_list + (m * NT + tile) * NN;
    int len = g_cnt[m * NT + tile];
    int s0 = (len * seg) / SSEG;
    int s1 = (len * (seg + 1)) / SSEG;

    __shared__ float4 sh4[CHUNK * PVEC];

    float T = 1.f;
    float accA = 0.f, accD = 0.f;
    float accS[CC];
    #pragma unroll
    for (int c = 0; c < CC; c++) accS[c] = 0.f;

    const float4* parm = g_par + m * NN * PVEC;

    for (int base = s0; base < s1; base += CHUNK) {
        int cn = min(CHUNK, s1 - base);
        __syncthreads();
        for (int i = t; i < cn * PVEC; i += 256) {
            int gsn = i / PVEC, part = i - gsn * PVEC;
            int entry = lp[base + gsn];
            sh4[i] = parm[entry * PVEC + part];
        }
        __syncthreads();

        if (T >= 1e-7f) {
            for (int j = 0; j < cn; j++) {
                float4 h0 = sh4[j * PVEC + 0];     // u, v, ia, ib
                float4 h1 = sh4[j * PVEC + 1];     // ic, op, z, pad
                float dx = fpx - h0.x;
                float dy = fpy - h0.y;
                float d2 = h0.z*dx*dx + h1.x*dy*dy + 2.f*h0.w*(dx*dy);
                if (d2 < CUT2) {
                    float al = fminf(h1.y * __expf(-0.5f * d2), 0.99f);
                    float w = T * al;
                    T -= w;
                    accA += w;
                    accD += w * h1.z;
                    #pragma unroll
                    for (int q = 0; q < 4; q++) {
                        float4 s4 = sh4[j * PVEC + 2 + q];
                        accS[q*4+0] += w * s4.x;
                        accS[q*4+1] += w * s4.y;
                        accS[q*4+2] += w * s4.z;
                        accS[q*4+3] += w * s4.w;
                    }
                }
            }
        }
        if (__syncthreads_and(T < 1e-7f)) break;
    }

    float* pp = g_part + ((m * NT + tile) * SSEG + seg) * (NF * 256);
    pp[0 * 256 + t] = accD;
    #pragma unroll
    for (int c = 0; c < CC; c++) pp[(1 + c) * 256 + t] = accS[c];
    pp[17 * 256 + t] = accA;
    pp[18 * 256 + t] = T;
}

// ---------------------------------------------------------------------------
// Kernel 5: fold segments in depth order, write final output
// grid (NT, MM), block 256
// ---------------------------------------------------------------------------
__global__ void combine_kernel(float* __restrict__ out)
{
    int m = blockIdx.y;
    int tile = blockIdx.x;
    int t = threadIdx.x;

    float acc[18];
    #pragma unroll
    for (int f = 0; f < 18; f++) acc[f] = 0.f;
    float Trun = 1.f;

    #pragma unroll
    for (int s = 0; s < SSEG; s++) {
        const float* pp = g_part + ((m * NT + tile) * SSEG + s) * (NF * 256);
        #pragma unroll
        for (int f = 0; f < 18; f++) acc[f] += Trun * pp[f * 256 + t];
        Trun *= pp[18 * 256 + t];
    }

    int px = (tile & 7) * 16 + (t & 15);
    int py = (tile >> 3) * 16 + (t >> 4);
    int pix = py * WW + px;

    // layout: depth [MM,1,H,W] | semantic [MM,CC,H,W] | alpha [MM,1,H,W]
    out[m * HW + pix] = acc[0];
    float* semo = out + MM * HW;
    #pragma unroll
    for (int c = 0; c < CC; c++)
        semo[(m * CC + c) * HW + pix] = acc[1 + c];
    out[MM * HW + MM * CC * HW + m * HW + pix] = acc[17];
}

// ---------------------------------------------------------------------------
// Launch: prep and sort are independent -> fork-join onto two streams so the
// graph runs them concurrently; bin joins both.
// ---------------------------------------------------------------------------
extern "C" void kernel_launch(void* const* d_in, const int* in_sizes, int n_in,
                              void* d_out, int out_size)
{
    const float* means  = (const float*)d_in[0];
    const float* scales = (const float*)d_in[1];
    const float* rots   = (const float*)d_in[2];
    const float* opac   = (const float*)d_in[3];
    const float* sem    = (const float*)d_in[4];
    const float* intr   = (const float*)d_in[5];
    const float* c2e    = (const float*)d_in[6];
    float* out = (float*)d_out;

    cudaStream_t s0 = 0;   // legacy default stream (capture stream in graph mode)
    cudaStream_t s1;
    cudaStreamCreateWithFlags(&s1, cudaStreamNonBlocking);
    cudaEvent_t eFork, eJoin;
    cudaEventCreateWithFlags(&eFork, cudaEventDisableTiming);
    cudaEventCreateWithFlags(&eJoin, cudaEventDisableTiming);

    // fork
    cudaEventRecord(eFork, s0);
    cudaStreamWaitEvent(s1, eFork, 0);

    prep_kernel<<<32, 128, 0, s0>>>(means, scales, rots, opac, sem, intr, c2e);
    sort_kernel<<<dim3(NN / 8, MM), 256, 0, s1>>>(means, c2e);

    // join
    cudaEventRecord(eJoin, s1);
    cudaStreamWaitEvent(s0, eJoin, 0);

    bin_kernel<<<MM * NT, 128, 0, s0>>>();
    render_kernel<<<dim3(8, 8, MM * SSEG), 256, 0, s0>>>();
    combine_kernel<<<dim3(NT, MM), 256, 0, s0>>>(out);

    cudaEventDestroy(eFork);
    cudaEventDestroy(eJoin);
    cudaStreamDestroy(s1);
}

// round 14
// speedup vs baseline: 1.0355x; 1.0355x over previous
#include <cuda_runtime.h>
#include <cuda_bf16.h>

// Problem constants (fixed shapes for this problem instance)
#define BB 1
#define NN 2048
#define CC 16
#define MM 2
#define HH 128
#define WW 128
#define HW (HH*WW)
#define NEARP 0.1f
#define FARP  100.0f

#define PVEC 6          // 6 float4 per gaussian: [u,v,ia,ib | ic,op,z,pad | sem0..15]
#define NT 64           // 8x8 tiles of 16x16 px per view
#define SSEG 4          // equal-length slices of each tile's list
#define NF 19           // partial record: depth, 16 sem, alpha, T
#define CUT2 20.0f      // d2 cutoff: skipped alpha < op*4.5e-5, ~20x under 1e-3 tol

__device__ float4 g_par [MM * NN * PVEC];   // per-(view,gaussian) packed params
__device__ float4 g_bbox[MM * NN];          // bbox (umin,umax,vmin,vmax), unsorted
__device__ int    g_perm[MM * NN];          // perm[rank] = gaussian index
__device__ int    g_list[MM * NT * NN];     // per-tile depth-ordered lists
__device__ int    g_cnt [MM * NT];          // per-tile list lengths
__device__ float  g_part[MM * NT * SSEG * NF * 256];  // segment partials

// ---------------------------------------------------------------------------
// Kernel 1: FUSED prep + sort. One warp per (view, gaussian).
// - all lanes: cooperative z-key build + 32-way rank scan + shfl reduce
// - lane 0: writes perm, runs full prep math (projection/conic/bbox)
// - lanes 0..15: parallel semantic feature copy
// grid (NN/8, MM), block 256 (8 warps)
// ---------------------------------------------------------------------------
__global__ void prep_sort_kernel(const float* __restrict__ means,
                                 const float* __restrict__ scales,
                                 const float* __restrict__ rots,
                                 const float* __restrict__ opac,
                                 const float* __restrict__ sem,
                                 const float* __restrict__ intr,
                                 const float* __restrict__ c2e)
{
    int m    = blockIdx.y;
    int t    = threadIdx.x;
    int lane = t & 31;
    int n    = blockIdx.x * 8 + (t >> 5);

    const float* A = c2e + m * 16;
    float a03=A[3], a13=A[7], a23=A[11];
    float w00=A[0], w01=A[4], w02=A[8];
    float w10=A[1], w11=A[5], w12=A[9];
    float w20=A[2], w21=A[6], w22=A[10];
    float e2 = -(w20*a03 + w21*a13 + w22*a23);

    __shared__ unsigned ks[NN];
    for (int i = t; i < NN; i += 256) {
        float zc = w20 * means[i*3+0] + w21 * means[i*3+1] + w22 * means[i*3+2] + e2;
        unsigned b = __float_as_uint(zc);
        ks[i] = b ^ (unsigned)(((int)b >> 31) | 0x80000000);  // monotonic key
    }
    __syncthreads();

    unsigned ki = ks[n];
    int r = 0;
    #pragma unroll 8
    for (int j = lane; j < NN; j += 32) {
        unsigned kj = ks[j];
        r += (kj < ki) || (kj == ki && j < n);
    }
    #pragma unroll
    for (int o = 16; o > 0; o >>= 1) r += __shfl_xor_sync(0xffffffffu, r, o);

    if (lane == 0) g_perm[m * NN + r] = n;

    // ---- prep (lane 0 of each warp) ----
    float* P = (float*)(g_par + (m * NN + n) * PVEC);

    if (lane == 0) {
        float e0 = -(w00*a03 + w01*a13 + w02*a23);
        float e1 = -(w10*a03 + w11*a13 + w12*a23);

        float mx = means[n*3+0], my = means[n*3+1], mz = means[n*3+2];
        float xc = w00*mx + w01*my + w02*mz + e0;
        float yc = w10*mx + w11*my + w12*mz + e1;
        float zc = w20*mx + w21*my + w22*mz + e2;

        const float* K = intr + m * 16;
        float fx = K[0], cx = K[2], fy = K[5], cy = K[6];

        float zs = fmaxf(zc, 1e-4f);
        float u = xc / zs * fx + cx;
        float v = yc / zs * fy + cy;

        float qw = rots[n*4+0], qx = rots[n*4+1], qy = rots[n*4+2], qz = rots[n*4+3];
        float qn = rsqrtf(qw*qw + qx*qx + qy*qy + qz*qz);
        qw *= qn; qx *= qn; qy *= qn; qz *= qn;
        float r00 = 1.f - 2.f*(qy*qy + qz*qz);
        float r01 = 2.f*(qx*qy - qz*qw);
        float r02 = 2.f*(qx*qz + qy*qw);
        float r10 = 2.f*(qx*qy + qz*qw);
        float r11 = 1.f - 2.f*(qx*qx + qz*qz);
        float r12 = 2.f*(qy*qz - qx*qw);
        float r20 = 2.f*(qx*qz - qy*qw);
        float r21 = 2.f*(qy*qz + qx*qw);
        float r22 = 1.f - 2.f*(qx*qx + qy*qy);

        float s0 = scales[n*3+0], s1 = scales[n*3+1], s2 = scales[n*3+2];
        float m00=r00*s0, m01=r01*s1, m02=r02*s2;
        float m10=r10*s0, m11=r11*s1, m12=r12*s2;
        float m20=r20*s0, m21=r21*s1, m22=r22*s2;
        float S00 = m00*m00 + m01*m01 + m02*m02;
        float S01 = m00*m10 + m01*m11 + m02*m12;
        float S02 = m00*m20 + m01*m21 + m02*m22;
        float S11 = m10*m10 + m11*m11 + m12*m12;
        float S12 = m10*m20 + m11*m21 + m12*m22;
        float S22 = m20*m20 + m21*m21 + m22*m22;

        float t00 = w00*S00 + w01*S01 + w02*S02;
        float t01 = w00*S01 + w01*S11 + w02*S12;
        float t02 = w00*S02 + w01*S12 + w02*S22;
        float t10 = w10*S00 + w11*S01 + w12*S02;
        float t11 = w10*S01 + w11*S11 + w12*S12;
        float t12 = w10*S02 + w11*S12 + w12*S22;
        float t20 = w20*S00 + w21*S01 + w22*S02;
        float t21 = w20*S01 + w21*S11 + w22*S12;
        float t22 = w20*S02 + w21*S12 + w22*S22;
        float c00 = t00*w00 + t01*w01 + t02*w02;
        float c01 = t00*w10 + t01*w11 + t02*w12;
        float c02 = t00*w20 + t01*w21 + t02*w22;
        float c11 = t10*w10 + t11*w11 + t12*w12;
        float c12 = t10*w20 + t11*w21 + t12*w22;
        float c22 = t20*w20 + t21*w21 + t22*w22;

        float iz = 1.f / zs;
        float jx = fx * iz;
        float jy = fy * iz;
        float jz0 = -fx * xc * iz * iz;
        float jz1 = -fy * yc * iz * iz;

        float cov00 = jx*jx*c00 + 2.f*jx*jz0*c02 + jz0*jz0*c22;
        float cov01 = jx*jy*c01 + jx*jz1*c02 + jz0*jy*c12 + jz0*jz1*c22;
        float cov11 = jy*jy*c11 + 2.f*jy*jz1*c12 + jz1*jz1*c22;

        float aa = fmaxf(cov00, 0.3f);
        float cc = fmaxf(cov11, 0.3f);
        float bb = cov01;
        float det = aa*cc - bb*bb;
        bool valid = (zc > 0.01f) && (det > 1e-8f);
        float dets = (det > 1e-8f) ? det : 1.f;
        float ia =  cc / dets;
        float ib = -bb / dets;
        float ic =  aa / dets;

        bool visible = valid && (zc > NEARP) &&
                       (u >= 0.f) && (u < (float)WW) &&
                       (v >= 0.f) && (v < (float)HH);

        float op = visible ? opac[n] : 0.f;

        float ex = sqrtf(CUT2 * aa);
        float ey = sqrtf(CUT2 * cc);
        float4 bbx;
        if (visible) bbx = make_float4(u - ex, u + ex, v - ey, v + ey);
        else         bbx = make_float4(1e9f, -1e9f, 1e9f, -1e9f);
        g_bbox[m * NN + n] = bbx;

        P[0] = u; P[1] = v; P[2] = ia; P[3] = ib;
        P[4] = ic; P[5] = op;
        P[6] = fminf(fmaxf(zc, NEARP), FARP);
        P[7] = 0.f;
    }
    // semantic copy: 16 lanes in parallel (independent of lane-0 math)
    if (lane < CC) P[8 + lane] = sem[n * CC + lane];
}

// ---------------------------------------------------------------------------
// Kernel 2: binning. One block (4 warps) per (view, tile). Each warp compacts
// its depth-quarter (gathering bbox via perm); block prefix; coalesced copy
// into one depth-ordered per-tile list. grid MM*NT = 128 blocks, 128 threads.
// ---------------------------------------------------------------------------
#define QN (NN / 4)     // 512 entries per warp-quarter

__global__ void bin_kernel()
{
    int m    = blockIdx.x / NT;
    int tile = blockIdx.x % NT;
    int wid  = threadIdx.x >> 5;
    int lane = threadIdx.x & 31;

    __shared__ int sh_idx[NN];      // 4 quarters x 512
    __shared__ int sh_cnt[4];

    float x0 = (float)((tile & 7) * 16);
    float y0 = (float)((tile >> 3) * 16);
    float x1 = x0 + 15.f;
    float y1 = y0 + 15.f;

    int base = wid * QN;
    int cnt = 0;
    #pragma unroll 4
    for (int it = 0; it < QN / 32; it++) {
        int j = base + it * 32 + lane;
        int idx = g_perm[m * NN + j];
        float4 bb = g_bbox[m * NN + idx];
        bool hit = (bb.x <= x1) && (bb.y >= x0) && (bb.z <= y1) && (bb.w >= y0);
        unsigned msk = __ballot_sync(0xffffffffu, hit);
        if (hit) sh_idx[base + cnt + __popc(msk & ((1u << lane) - 1u))] = idx;
        cnt += __popc(msk);
    }
    if (lane == 0) sh_cnt[wid] = cnt;
    __syncthreads();

    int c0 = sh_cnt[0], c1 = sh_cnt[1], c2 = sh_cnt[2], c3 = sh_cnt[3];
    int off1 = c0, off2 = c0 + c1, off3 = c0 + c1 + c2;
    int total = off3 + c3;

    int* lp = g_list + (m * NT + tile) * NN;
    for (int i = threadIdx.x; i < c0; i += 128) lp[i]        = sh_idx[0*QN + i];
    for (int i = threadIdx.x; i < c1; i += 128) lp[off1 + i] = sh_idx[1*QN + i];
    for (int i = threadIdx.x; i < c2; i += 128) lp[off2 + i] = sh_idx[2*QN + i];
    for (int i = threadIdx.x; i < c3; i += 128) lp[off3 + i] = sh_idx[3*QN + i];
    if (threadIdx.x == 0) g_cnt[m * NT + tile] = total;
}

// ---------------------------------------------------------------------------
// Kernel 3: segmented front-to-back compositing (16x16 px tile, 256 threads).
// Equal-length slices of each tile's depth-ordered list; segment-local T.
// grid (8, 8, MM*SSEG), block 256.
// ---------------------------------------------------------------------------
#define CHUNK 128

__global__ void __launch_bounds__(256, 4) render_kernel()
{
    int mz  = blockIdx.z;
    int m   = mz / SSEG;
    int seg = mz % SSEG;
    int t   = threadIdx.x;
    float fpx = (float)(blockIdx.x * 16 + (t & 15));
    float fpy = (float)(blockIdx.y * 16 + (t >> 4));

    int tile = blockIdx.y * 8 + blockIdx.x;
    const int* lp = g_list + (m * NT + tile) * NN;
    int len = g_cnt[m * NT + tile];
    int s0 = (len * seg) / SSEG;
    int s1 = (len * (seg + 1)) / SSEG;

    __shared__ float4 sh4[CHUNK * PVEC];

    float T = 1.f;
    float accA = 0.f, accD = 0.f;
    float accS[CC];
    #pragma unroll
    for (int c = 0; c < CC; c++) accS[c] = 0.f;

    const float4* parm = g_par + m * NN * PVEC;

    for (int base = s0; base < s1; base += CHUNK) {
        int cn = min(CHUNK, s1 - base);
        __syncthreads();
        for (int i = t; i < cn * PVEC; i += 256) {
            int gsn = i / PVEC, part = i - gsn * PVEC;
            int entry = lp[base + gsn];
            sh4[i] = parm[entry * PVEC + part];
        }
        __syncthreads();

        if (T >= 1e-7f) {
            for (int j = 0; j < cn; j++) {
                float4 h0 = sh4[j * PVEC + 0];     // u, v, ia, ib
                float4 h1 = sh4[j * PVEC + 1];     // ic, op, z, pad
                float dx = fpx - h0.x;
                float dy = fpy - h0.y;
                float d2 = h0.z*dx*dx + h1.x*dy*dy + 2.f*h0.w*(dx*dy);
                if (d2 < CUT2) {
                    float al = fminf(h1.y * __expf(-0.5f * d2), 0.99f);
                    float w = T * al;
                    T -= w;
                    accA += w;
                    accD += w * h1.z;
                    #pragma unroll
                    for (int q = 0; q < 4; q++) {
                        float4 s4 = sh4[j * PVEC + 2 + q];
                        accS[q*4+0] += w * s4.x;
                        accS[q*4+1] += w * s4.y;
                        accS[q*4+2] += w * s4.z;
                        accS[q*4+3] += w * s4.w;
                    }
                }
            }
        }
        if (__syncthreads_and(T < 1e-7f)) break;
    }

    float* pp = g_part + ((m * NT + tile) * SSEG + seg) * (NF * 256);
    pp[0 * 256 + t] = accD;
    #pragma unroll
    for (int c = 0; c < CC; c++) pp[(1 + c) * 256 + t] = accS[c];
    pp[17 * 256 + t] = accA;
    pp[18 * 256 + t] = T;
}

// ---------------------------------------------------------------------------
// Kernel 4: fold segments in depth order, write final output
// grid (NT, MM), block 256
// ---------------------------------------------------------------------------
__global__ void combine_kernel(float* __restrict__ out)
{
    int m = blockIdx.y;
    int tile = blockIdx.x;
    int t = threadIdx.x;

    float acc[18];
    #pragma unroll
    for (int f = 0; f < 18; f++) acc[f] = 0.f;
    float Trun = 1.f;

    #pragma unroll
    for (int s = 0; s < SSEG; s++) {
        const float* pp = g_part + ((m * NT + tile) * SSEG + s) * (NF * 256);
        #pragma unroll
        for (int f = 0; f < 18; f++) acc[f] += Trun * pp[f * 256 + t];
        Trun *= pp[18 * 256 + t];
    }

    int px = (tile & 7) * 16 + (t & 15);
    int py = (tile >> 3) * 16 + (t >> 4);
    int pix = py * WW + px;

    // layout: depth [MM,1,H,W] | semantic [MM,CC,H,W] | alpha [MM,1,H,W]
    out[m * HW + pix] = acc[0];
    float* semo = out + MM * HW;
    #pragma unroll
    for (int c = 0; c < CC; c++)
        semo[(m * CC + c) * HW + pix] = acc[1 + c];
    out[MM * HW + MM * CC * HW + m * HW + pix] = acc[17];
}

// ---------------------------------------------------------------------------
extern "C" void kernel_launch(void* const* d_in, const int* in_sizes, int n_in,
                              void* d_out, int out_size)
{
    const float* means  = (const float*)d_in[0];
    const float* scales = (const float*)d_in[1];
    const float* rots   = (const float*)d_in[2];
    const float* opac   = (const float*)d_in[3];
    const float* sem    = (const float*)d_in[4];
    const float* intr   = (const float*)d_in[5];
    const float* c2e    = (const float*)d_in[6];
    float* out = (float*)d_out;

    prep_sort_kernel<<<dim3(NN / 8, MM), 256>>>(means, scales, rots, opac, sem, intr, c2e);
    bin_kernel<<<MM * NT, 128>>>();
    render_kernel<<<dim3(8, 8, MM * SSEG), 256>>>();
    combine_kernel<<<dim3(NT, MM), 256>>>(out);
}

// round 15
// speedup vs baseline: 1.0994x; 1.0617x over previous
#include <cuda_runtime.h>
#include <cuda_bf16.h>

// Problem constants (fixed shapes for this problem instance)
#define BB 1
#define NN 2048
#define CC 16
#define MM 2
#define HH 128
#define WW 128
#define HW (HH*WW)
#define NEARP 0.1f
#define FARP  100.0f

#define PVEC 6          // 6 float4 per gaussian: [u,v,ia,ib | ic,op,z,pad | sem0..15]
#define NT 64           // 8x8 tiles of 16x16 px per view
#define SSEG 4          // equal-length slices of each tile's list
#define NF 19           // partial record: depth, 16 sem, alpha, T
#define CUT2 20.0f      // d2 cutoff: skipped alpha < op*4.5e-5, ~20x under 1e-3 tol
#define NFG 3           // combine field groups (6 fields each)

__device__ float4 g_par [MM * NN * PVEC];   // per-(view,gaussian) packed params
__device__ float4 g_bbox[MM * NN];          // bbox (umin,umax,vmin,vmax), unsorted
__device__ int    g_perm[MM * NN];          // perm[rank] = gaussian index
__device__ int    g_list[MM * NT * NN];     // per-tile depth-ordered lists
__device__ int    g_cnt [MM * NT];          // per-tile list lengths
__device__ float  g_part[MM * NT * SSEG * NF * 256];  // segment partials

// ---------------------------------------------------------------------------
// Kernel 1: per-(view, gaussian) preprocessing
// ---------------------------------------------------------------------------
__global__ void prep_kernel(const float* __restrict__ means,
                            const float* __restrict__ scales,
                            const float* __restrict__ rots,
                            const float* __restrict__ opac,
                            const float* __restrict__ sem,
                            const float* __restrict__ intr,
                            const float* __restrict__ c2e)
{
    int idx = blockIdx.x * blockDim.x + threadIdx.x;
    if (idx >= MM * NN) return;
    int m = idx / NN;
    int n = idx % NN;

    // cam2ego (rigid) -> ego2cam: E_R = R^T, E_t = -R^T t
    const float* A = c2e + m * 16;
    float a03=A[3], a13=A[7], a23=A[11];
    float w00=A[0], w01=A[4], w02=A[8];
    float w10=A[1], w11=A[5], w12=A[9];
    float w20=A[2], w21=A[6], w22=A[10];
    float e0 = -(w00*a03 + w01*a13 + w02*a23);
    float e1 = -(w10*a03 + w11*a13 + w12*a23);
    float e2 = -(w20*a03 + w21*a13 + w22*a23);

    float mx = means[n*3+0], my = means[n*3+1], mz = means[n*3+2];
    float xc = w00*mx + w01*my + w02*mz + e0;
    float yc = w10*mx + w11*my + w12*mz + e1;
    float zc = w20*mx + w21*my + w22*mz + e2;

    const float* K = intr + m * 16;
    float fx = K[0], cx = K[2], fy = K[5], cy = K[6];

    float zs = fmaxf(zc, 1e-4f);
    float u = xc / zs * fx + cx;
    float v = yc / zs * fy + cy;

    // quaternion (w,x,y,z) -> rotation matrix
    float qw = rots[n*4+0], qx = rots[n*4+1], qy = rots[n*4+2], qz = rots[n*4+3];
    float qn = rsqrtf(qw*qw + qx*qx + qy*qy + qz*qz);
    qw *= qn; qx *= qn; qy *= qn; qz *= qn;
    float r00 = 1.f - 2.f*(qy*qy + qz*qz);
    float r01 = 2.f*(qx*qy - qz*qw);
    float r02 = 2.f*(qx*qz + qy*qw);
    float r10 = 2.f*(qx*qy + qz*qw);
    float r11 = 1.f - 2.f*(qx*qx + qz*qz);
    float r12 = 2.f*(qy*qz - qx*qw);
    float r20 = 2.f*(qx*qz - qy*qw);
    float r21 = 2.f*(qy*qz + qx*qw);
    float r22 = 1.f - 2.f*(qx*qx + qy*qy);

    float s0 = scales[n*3+0], s1 = scales[n*3+1], s2 = scales[n*3+2];
    float m00=r00*s0, m01=r01*s1, m02=r02*s2;
    float m10=r10*s0, m11=r11*s1, m12=r12*s2;
    float m20=r20*s0, m21=r21*s1, m22=r22*s2;
    // Sigma = RS RS^T
    float S00 = m00*m00 + m01*m01 + m02*m02;
    float S01 = m00*m10 + m01*m11 + m02*m12;
    float S02 = m00*m20 + m01*m21 + m02*m22;
    float S11 = m10*m10 + m11*m11 + m12*m12;
    float S12 = m10*m20 + m11*m21 + m12*m22;
    float S22 = m20*m20 + m21*m21 + m22*m22;

    // Sigma_cam = Wc * Sigma * Wc^T
    float t00 = w00*S00 + w01*S01 + w02*S02;
    float t01 = w00*S01 + w01*S11 + w02*S12;
    float t02 = w00*S02 + w01*S12 + w02*S22;
    float t10 = w10*S00 + w11*S01 + w12*S02;
    float t11 = w10*S01 + w11*S11 + w12*S12;
    float t12 = w10*S02 + w11*S12 + w12*S22;
    float t20 = w20*S00 + w21*S01 + w22*S02;
    float t21 = w20*S01 + w21*S11 + w22*S12;
    float t22 = w20*S02 + w21*S12 + w22*S22;
    float c00 = t00*w00 + t01*w01 + t02*w02;
    float c01 = t00*w10 + t01*w11 + t02*w12;
    float c02 = t00*w20 + t01*w21 + t02*w22;
    float c11 = t10*w10 + t11*w11 + t12*w12;
    float c12 = t10*w20 + t11*w21 + t12*w22;
    float c22 = t20*w20 + t21*w21 + t22*w22;

    // J projection
    float iz = 1.f / zs;
    float jx = fx * iz;
    float jy = fy * iz;
    float jz0 = -fx * xc * iz * iz;
    float jz1 = -fy * yc * iz * iz;

    float cov00 = jx*jx*c00 + 2.f*jx*jz0*c02 + jz0*jz0*c22;
    float cov01 = jx*jy*c01 + jx*jz1*c02 + jz0*jy*c12 + jz0*jz1*c22;
    float cov11 = jy*jy*c11 + 2.f*jy*jz1*c12 + jz1*jz1*c22;

    float aa = fmaxf(cov00, 0.3f);
    float cc = fmaxf(cov11, 0.3f);
    float bb = cov01;
    float det = aa*cc - bb*bb;
    bool valid = (zc > 0.01f) && (det > 1e-8f);
    float dets = (det > 1e-8f) ? det : 1.f;
    float ia =  cc / dets;
    float ib = -bb / dets;
    float ic =  aa / dets;

    bool visible = valid && (zc > NEARP) &&
                   (u >= 0.f) && (u < (float)WW) &&
                   (v >= 0.f) && (v < (float)HH);

    float op = visible ? opac[n] : 0.f;

    // bbox of the d2<CUT2 ellipse (axis-aligned extents)
    float ex = sqrtf(CUT2 * aa);
    float ey = sqrtf(CUT2 * cc);
    float4 bbx;
    if (visible) bbx = make_float4(u - ex, u + ex, v - ey, v + ey);
    else         bbx = make_float4(1e9f, -1e9f, 1e9f, -1e9f);
    g_bbox[m * NN + n] = bbx;

    float* P = (float*)(g_par + (m * NN + n) * PVEC);
    P[0] = u; P[1] = v; P[2] = ia; P[3] = ib;
    P[4] = ic; P[5] = op;
    P[6] = fminf(fmaxf(zc, NEARP), FARP);
    P[7] = 0.f;
    const float* sm = sem + n * CC;
    #pragma unroll
    for (int c = 0; c < CC; c++) P[8 + c] = sm[c];
}

// ---------------------------------------------------------------------------
// Kernel 2: warp-per-gaussian stable rank sort (z ascending, index tiebreak).
// Computes z directly from means/c2e. Writes perm only.
// grid (NN/8, MM), block 256 (8 warps)
// ---------------------------------------------------------------------------
__global__ void sort_kernel(const float* __restrict__ means,
                            const float* __restrict__ c2e)
{
    int m    = blockIdx.y;
    int t    = threadIdx.x;
    int lane = t & 31;
    int n    = blockIdx.x * 8 + (t >> 5);

    const float* A = c2e + m * 16;
    float w20 = A[2], w21 = A[6], w22 = A[10];
    float e2  = -(w20 * A[3] + w21 * A[7] + w22 * A[11]);

    __shared__ unsigned ks[NN];
    for (int i = t; i < NN; i += 256) {
        float zc = w20 * means[i*3+0] + w21 * means[i*3+1] + w22 * means[i*3+2] + e2;
        unsigned b = __float_as_uint(zc);
        ks[i] = b ^ (unsigned)(((int)b >> 31) | 0x80000000);  // monotonic key
    }
    __syncthreads();

    unsigned ki = ks[n];
    int r = 0;
    #pragma unroll 8
    for (int j = lane; j < NN; j += 32) {
        unsigned kj = ks[j];
        r += (kj < ki) || (kj == ki && j < n);
    }
    #pragma unroll
    for (int o = 16; o > 0; o >>= 1) r += __shfl_xor_sync(0xffffffffu, r, o);

    if (lane == 0) g_perm[m * NN + r] = n;
}

// ---------------------------------------------------------------------------
// Kernel 3: binning. One block (4 warps) per (view, tile). Each warp compacts
// its depth-quarter (gathering bbox via perm); block prefix; coalesced copy
// into one depth-ordered per-tile list. grid MM*NT = 128 blocks, 128 threads.
// ---------------------------------------------------------------------------
#define QN (NN / 4)     // 512 entries per warp-quarter

__global__ void bin_kernel()
{
    int m    = blockIdx.x / NT;
    int tile = blockIdx.x % NT;
    int wid  = threadIdx.x >> 5;
    int lane = threadIdx.x & 31;

    __shared__ int sh_idx[NN];      // 4 quarters x 512
    __shared__ int sh_cnt[4];

    float x0 = (float)((tile & 7) * 16);
    float y0 = (float)((tile >> 3) * 16);
    float x1 = x0 + 15.f;
    float y1 = y0 + 15.f;

    int base = wid * QN;
    int cnt = 0;
    #pragma unroll 4
    for (int it = 0; it < QN / 32; it++) {
        int j = base + it * 32 + lane;
        int idx = g_perm[m * NN + j];
        float4 bb = g_bbox[m * NN + idx];
        bool hit = (bb.x <= x1) && (bb.y >= x0) && (bb.z <= y1) && (bb.w >= y0);
        unsigned msk = __ballot_sync(0xffffffffu, hit);
        if (hit) sh_idx[base + cnt + __popc(msk & ((1u << lane) - 1u))] = idx;
        cnt += __popc(msk);
    }
    if (lane == 0) sh_cnt[wid] = cnt;
    __syncthreads();

    int c0 = sh_cnt[0], c1 = sh_cnt[1], c2 = sh_cnt[2], c3 = sh_cnt[3];
    int off1 = c0, off2 = c0 + c1, off3 = c0 + c1 + c2;
    int total = off3 + c3;

    int* lp = g_list + (m * NT + tile) * NN;
    for (int i = threadIdx.x; i < c0; i += 128) lp[i]        = sh_idx[0*QN + i];
    for (int i = threadIdx.x; i < c1; i += 128) lp[off1 + i] = sh_idx[1*QN + i];
    for (int i = threadIdx.x; i < c2; i += 128) lp[off2 + i] = sh_idx[2*QN + i];
    for (int i = threadIdx.x; i < c3; i += 128) lp[off3 + i] = sh_idx[3*QN + i];
    if (threadIdx.x == 0) g_cnt[m * NT + tile] = total;
}

// ---------------------------------------------------------------------------
// Kernel 4: segmented front-to-back compositing (16x16 px tile, 256 threads).
// Equal-length slices of each tile's depth-ordered list; segment-local T.
// grid (8, 8, MM*SSEG), block 256.
// ---------------------------------------------------------------------------
#define CHUNK 128

__global__ void __launch_bounds__(256, 4) render_kernel()
{
    int mz  = blockIdx.z;
    int m   = mz / SSEG;
    int seg = mz % SSEG;
    int t   = threadIdx.x;
    float fpx = (float)(blockIdx.x * 16 + (t & 15));
    float fpy = (float)(blockIdx.y * 16 + (t >> 4));

    int tile = blockIdx.y * 8 + blockIdx.x;
    const int* lp = g_list + (m * NT + tile) * NN;
    int len = g_cnt[m * NT + tile];
    int s0 = (len * seg) / SSEG;
    int s1 = (len * (seg + 1)) / SSEG;

    __shared__ float4 sh4[CHUNK * PVEC];

    float T = 1.f;
    float accA = 0.f, accD = 0.f;
    float accS[CC];
    #pragma unroll
    for (int c = 0; c < CC; c++) accS[c] = 0.f;

    const float4* parm = g_par + m * NN * PVEC;

    for (int base = s0; base < s1; base += CHUNK) {
        int cn = min(CHUNK, s1 - base);
        __syncthreads();
        for (int i = t; i < cn * PVEC; i += 256) {
            int gsn = i / PVEC, part = i - gsn * PVEC;
            int entry = lp[base + gsn];
            sh4[i] = parm[entry * PVEC + part];
        }
        __syncthreads();

        if (T >= 1e-7f) {
            for (int j = 0; j < cn; j++) {
                float4 h0 = sh4[j * PVEC + 0];     // u, v, ia, ib
                float4 h1 = sh4[j * PVEC + 1];     // ic, op, z, pad
                float dx = fpx - h0.x;
                float dy = fpy - h0.y;
                float d2 = h0.z*dx*dx + h1.x*dy*dy + 2.f*h0.w*(dx*dy);
                if (d2 < CUT2) {
                    float al = fminf(h1.y * __expf(-0.5f * d2), 0.99f);
                    float w = T * al;
                    T -= w;
                    accA += w;
                    accD += w * h1.z;
                    #pragma unroll
                    for (int q = 0; q < 4; q++) {
                        float4 s4 = sh4[j * PVEC + 2 + q];
                        accS[q*4+0] += w * s4.x;
                        accS[q*4+1] += w * s4.y;
                        accS[q*4+2] += w * s4.z;
                        accS[q*4+3] += w * s4.w;
                    }
                }
            }
        }
        if (__syncthreads_and(T < 1e-7f)) break;
    }

    float* pp = g_part + ((m * NT + tile) * SSEG + seg) * (NF * 256);
    pp[0 * 256 + t] = accD;
    #pragma unroll
    for (int c = 0; c < CC; c++) pp[(1 + c) * 256 + t] = accS[c];
    pp[17 * 256 + t] = accA;
    pp[18 * 256 + t] = T;
}

// ---------------------------------------------------------------------------
// Kernel 5: fold segments in depth order, write final output.
// Field-split over blockIdx.z (NFG groups of 6 fields) for 3x parallelism.
// grid (NT, MM, NFG), block 256.
// ---------------------------------------------------------------------------
__global__ void combine_kernel(float* __restrict__ out)
{
    int tile = blockIdx.x;
    int m    = blockIdx.y;
    int fg   = blockIdx.z;
    int t    = threadIdx.x;
    int f0   = fg * 6;

    const float* pb = g_part + (m * NT + tile) * SSEG * (NF * 256);

    // transmittance of each segment (shared across field groups)
    float T0 = pb[0 * (NF*256) + 18*256 + t];
    float T1 = pb[1 * (NF*256) + 18*256 + t];
    float T2 = pb[2 * (NF*256) + 18*256 + t];

    float acc[6];
    #pragma unroll
    for (int f = 0; f < 6; f++) {
        float a = pb[0 * (NF*256) + (f0 + f) * 256 + t];
        a +=      T0 * pb[1 * (NF*256) + (f0 + f) * 256 + t];
        a += T0 * T1 * pb[2 * (NF*256) + (f0 + f) * 256 + t];
        a += T0 * T1 * T2 * pb[3 * (NF*256) + (f0 + f) * 256 + t];
        acc[f] = a;
    }

    int px = (tile & 7) * 16 + (t & 15);
    int py = (tile >> 3) * 16 + (t >> 4);
    int pix = py * WW + px;

    // layout: depth [MM,1,H,W] | semantic [MM,CC,H,W] | alpha [MM,1,H,W]
    float* semo = out + MM * HW;
    #pragma unroll
    for (int f = 0; f < 6; f++) {
        int fld = f0 + f;
        if (fld == 0)       out[m * HW + pix] = acc[f];
        else if (fld < 17)  semo[(m * CC + (fld - 1)) * HW + pix] = acc[f];
        else                out[MM * HW + MM * CC * HW + m * HW + pix] = acc[f];
    }
}

// ---------------------------------------------------------------------------
extern "C" void kernel_launch(void* const* d_in, const int* in_sizes, int n_in,
                              void* d_out, int out_size)
{
    const float* means  = (const float*)d_in[0];
    const float* scales = (const float*)d_in[1];
    const float* rots   = (const float*)d_in[2];
    const float* opac   = (const float*)d_in[3];
    const float* sem    = (const float*)d_in[4];
    const float* intr   = (const float*)d_in[5];
    const float* c2e    = (const float*)d_in[6];
    float* out = (float*)d_out;

    prep_kernel<<<32, 128>>>(means, scales, rots, opac, sem, intr, c2e);
    sort_kernel<<<dim3(NN / 8, MM), 256>>>(means, c2e);
    bin_kernel<<<MM * NT, 128>>>();
    render_kernel<<<dim3(8, 8, MM * SSEG), 256>>>();
    combine_kernel<<<dim3(NT, MM, NFG), 256>>>(out);
}